// round 2
// baseline (speedup 1.0000x reference)
#include <cuda_runtime.h>
#include <math.h>

// ---------------- problem dims ----------------
#define Bb    8
#define Nn    1024
#define Kk    32
#define Dd    256
#define Hh    8
#define DHh   32
#define TDIMc 16
#define NBc   32
#define HIDc  128
#define Lc    4
#define NSc   128
#define SHDc  9
#define EINc  304
#define Mm    (Bb*Nn)

// ---------------- scratch (device globals; no allocs allowed) ----------------
__device__ int   g_src [Mm*Kk];
__device__ float g_r   [Mm*Kk];
__device__ float g_cutb[Mm*Kk];
__device__ float g_sh  [Mm*Kk*SHDc];
__device__ float g_node[Mm*Dd];
__device__ float g_q   [Mm*Dd];
__device__ float g_vn  [Mm*Dd];
__device__ float g_agg [Mm*Dd];
__device__ float g_ssrc[Mm*HIDc];
__device__ float g_sdst[Mm*HIDc];
__device__ float g_qk  [Mm*HIDc*Hh];   // [m][j][h]
__device__ float g_tpart[Lc*Bb*HIDc];

__device__ __forceinline__ float gelu_tanh(float v) {
    float c = 0.7978845608028654f * (v + 0.044715f * v * v * v);
    return 0.5f * v * (1.0f + tanhf(c));
}

// ---------------- kNN: brute-force top-K smallest d2, stable tie-break ----------------
__global__ void knn_kernel(const float* __restrict__ x) {
    __shared__ float px[Nn], py[Nn], pz[Nn];
    int b = blockIdx.y;
    const float* xb = x + (size_t)b * Nn * 3;
    for (int i = threadIdx.x; i < Nn; i += blockDim.x) {
        px[i] = xb[i*3+0]; py[i] = xb[i*3+1]; pz[i] = xb[i*3+2];
    }
    __syncthreads();
    int n = blockIdx.x * blockDim.x + threadIdx.x;
    float qx = px[n], qy = py[n], qz = pz[n];
    float bd[Kk]; int bi[Kk];
    #pragma unroll
    for (int i = 0; i < Kk; i++) { bd[i] = 3.4e38f; bi[i] = 0x7fffffff; }
    for (int j = 0; j < Nn; j++) {
        float dx = qx - px[j], dy = qy - py[j], dz = qz - pz[j];
        float d2 = dx*dx + dy*dy + dz*dz;
        if (d2 < bd[Kk-1] || (d2 == bd[Kk-1] && j < bi[Kk-1])) {
            int p = Kk - 1;
            while (p > 0 && (bd[p-1] > d2 || (bd[p-1] == d2 && bi[p-1] > j))) {
                bd[p] = bd[p-1]; bi[p] = bi[p-1]; p--;
            }
            bd[p] = d2; bi[p] = j;
        }
    }
    int base = (b * Nn + n) * Kk;
    for (int i = 0; i < Kk; i++) g_src[base + i] = bi[i];
}

// ---------------- per-edge geometry: r, cutoff, spherical harmonics ----------------
__global__ void geom_kernel(const float* __restrict__ x) {
    int gid = blockIdx.x * blockDim.x + threadIdx.x;
    if (gid >= Mm * Kk) return;
    int m = gid / Kk;
    int b = m / Nn, n = m % Nn;
    int s = g_src[gid];
    const float* xb = x + (size_t)b * Nn * 3;
    float vx = xb[n*3+0] - xb[s*3+0];
    float vy = xb[n*3+1] - xb[s*3+1];
    float vz = xb[n*3+2] - xb[s*3+2];
    float r = sqrtf(vx*vx + vy*vy + vz*vz);
    g_r[gid] = r;
    float xc = 10.0f - 5.0f * r;                 // 10*(1 - r/2)
    g_cutb[gid] = (xc > 0.0f) ? 1.4f * expf(-1.0f / xc) : 0.0f;
    float inv = 1.0f / fmaxf(r, 1e-9f);
    float ux = vx * inv, uy = vy * inv, uz = vz * inv;
    const float s3 = 1.7320508075688772f;   // sqrt(3)
    const float s15 = 3.872983346207417f;   // sqrt(15)
    const float h5 = 1.118033988749895f;    // 0.5*sqrt(5)
    const float h15 = 1.9364916731037085f;  // 0.5*sqrt(15)
    float* sh = g_sh + (size_t)gid * SHDc;
    sh[0] = 1.0f;
    sh[1] = s3 * ux; sh[2] = s3 * uy; sh[3] = s3 * uz;
    sh[4] = s15 * ux * uy;
    sh[5] = s15 * uy * uz;
    sh[6] = h5 * (3.0f * uz * uz - 1.0f);
    sh[7] = s15 * ux * uz;
    sh[8] = h15 * (ux * ux - uy * uy);
}

// ---------------- node embedding: [y,t] @ W_embed (19x256) ----------------
__global__ void embed_kernel(const float* __restrict__ y, const float* __restrict__ t,
                             const float* __restrict__ W_embed) {
    __shared__ float in[3 + TDIMc];
    int m = blockIdx.x;
    int b = m / Nn;
    int tid = threadIdx.x;
    if (tid < 3) in[tid] = y[(size_t)m * 3 + tid];
    else if (tid < 3 + TDIMc) in[tid] = t[b * TDIMc + (tid - 3)];
    __syncthreads();
    float acc = 0.0f;
    #pragma unroll
    for (int i = 0; i < 3 + TDIMc; i++) acc += in[i] * W_embed[i * Dd + tid];
    g_node[(size_t)m * Dd + tid] = acc;
}

// ---------------- tpart[l][b][j] = bk1[l][j] + t[b]@Wk1[l][32:48][j] ----------------
__global__ void tpart_kernel(const float* __restrict__ t, const float* __restrict__ Wk1,
                             const float* __restrict__ bk1) {
    int l = blockIdx.x / Bb, b = blockIdx.x % Bb;
    int j = threadIdx.x;
    float acc = bk1[l * HIDc + j];
    #pragma unroll
    for (int i = 0; i < TDIMc; i++)
        acc += t[b * TDIMc + i] * Wk1[((size_t)l * EINc + 32 + i) * HIDc + j];
    g_tpart[(l * Bb + b) * HIDc + j] = acc;
}

// ---------------- generic tiled SGEMM, 64x64 tile, 4x4 per thread ----------------
// C[m*cms + n*cns] = sum_k A[m*lda + k] * W[k*wks + n*wns]   (+ residual/activation)
// actmode 0: plain. actmode 1: v = resid + acc; n<64 gelu, 64<=n<128 tanh, else id.
// Requires: M % 64 == 0, N % 64 == 0, K % 16 == 0.
__global__ void gemm_kernel(const float* __restrict__ A, int lda,
                            const float* __restrict__ W, int wks, int wns,
                            float* __restrict__ C, int cms, int cns,
                            int M, int Kd, int Nd,
                            const float* __restrict__ resid, int actmode) {
    __shared__ float As[16][65];
    __shared__ float Ws[16][65];
    int m0 = blockIdx.x * 64, n0 = blockIdx.y * 64;
    int tx = threadIdx.x & 15, ty = threadIdx.x >> 4;
    float acc[4][4];
    #pragma unroll
    for (int i = 0; i < 4; i++)
        #pragma unroll
        for (int j = 0; j < 4; j++) acc[i][j] = 0.0f;

    for (int k0 = 0; k0 < Kd; k0 += 16) {
        for (int i = threadIdx.x; i < 64 * 16; i += 256) {
            int mi = i >> 4, kk = i & 15;
            As[kk][mi] = A[(size_t)(m0 + mi) * lda + k0 + kk];
        }
        for (int i = threadIdx.x; i < 64 * 16; i += 256) {
            int kk = i >> 6, ni = i & 63;
            Ws[kk][ni] = W[(size_t)(k0 + kk) * wks + (size_t)(n0 + ni) * wns];
        }
        __syncthreads();
        #pragma unroll
        for (int kk = 0; kk < 16; kk++) {
            float a[4], bw[4];
            #pragma unroll
            for (int i = 0; i < 4; i++) a[i] = As[kk][ty * 4 + i];
            #pragma unroll
            for (int j = 0; j < 4; j++) bw[j] = Ws[kk][tx * 4 + j];
            #pragma unroll
            for (int i = 0; i < 4; i++)
                #pragma unroll
                for (int j = 0; j < 4; j++) acc[i][j] += a[i] * bw[j];
        }
        __syncthreads();
    }
    #pragma unroll
    for (int i = 0; i < 4; i++) {
        int m = m0 + ty * 4 + i;
        #pragma unroll
        for (int j = 0; j < 4; j++) {
            int n = n0 + tx * 4 + j;
            float v = acc[i][j];
            if (actmode == 1) {
                v += resid[(size_t)m * cms + (size_t)n * cns];
                if (n < 64) v = gelu_tanh(v);
                else if (n < 128) v = tanhf(v);
            }
            C[(size_t)m * cms + (size_t)n * cns] = v;
        }
    }
}

// ---------------- fused per-node edge/attention kernel (one block per node) --------
__global__ void edge_kernel(const float* __restrict__ Wk1, const float* __restrict__ Wv,
                            int l) {
    __shared__ float s_wk1[NBc * HIDc];    // 16 KB  [i][j]
    __shared__ float s_h  [Kk * HIDc];     // 16 KB  [k][j]
    __shared__ float s_rbf[Kk * NBc];      // 4 KB   [k][i]
    __shared__ float s_qk [HIDc * Hh];     // 4 KB   [j][h]
    __shared__ float s_al [Kk * Hh];       // 1 KB   [k][h] logits -> alpha
    __shared__ float s_shl[Kk * SHDc];     // [k][s]
    __shared__ float s_base[HIDc];
    __shared__ float s_r[Kk], s_cut[Kk];
    __shared__ int   s_id[Kk];

    int m = blockIdx.x;
    int b = m / Nn;
    int tid = threadIdx.x;
    const float* Wk1l = Wk1 + (size_t)l * EINc * HIDc;          // rows 0..31 = rbf part
    const float* WvSh = Wv + ((size_t)l * (Dd + SHDc) + Dd) * Dd;
    const float* tpl  = g_tpart + (l * Bb + b) * HIDc;

    if (tid < Kk) {
        s_id[tid]  = g_src [m * Kk + tid];
        s_r[tid]   = g_r   [m * Kk + tid];
        s_cut[tid] = g_cutb[m * Kk + tid];
    }
    if (tid < HIDc) s_base[tid] = g_sdst[(size_t)m * HIDc + tid] + tpl[tid];
    for (int i = tid; i < HIDc * Hh; i += 256) s_qk[i] = g_qk[(size_t)m * HIDc * Hh + i];
    for (int i = tid; i < Kk * SHDc; i += 256) s_shl[i] = g_sh[(size_t)m * Kk * SHDc + i];
    for (int i = tid; i < NBc * HIDc; i += 256) s_wk1[i] = Wk1l[i];
    __syncthreads();

    // rbf (gaussian basis * cutoff, matches e3nn soft_one_hot * sqrt(NB)*0.95)
    const float ISTEP = 15.5f;                           // 1/(2/31)
    const float RBFC  = 5.656854249492381f * 0.95f / 1.12f; // sqrt(32)*0.95/1.12
    for (int i = tid; i < Kk * NBc; i += 256) {
        int k = i >> 5, ii = i & 31;
        float d = s_r[k] * ISTEP - (float)ii;
        s_rbf[i] = expf(-d * d) * RBFC * s_cut[k];
    }
    __syncthreads();

    // h = gelu(rbf@Wk1r + s_src[src] + s_dst + tpart)   [K=32, HID=128]
    const float* ssrcB = g_ssrc + (size_t)b * Nn * HIDc;
    #pragma unroll
    for (int it = 0; it < 16; it++) {
        int idx = tid + it * 256;
        int k = idx >> 7, j = idx & 127;
        float acc = s_base[j] + ssrcB[(size_t)s_id[k] * HIDc + j];
        #pragma unroll
        for (int ii = 0; ii < NBc; ii++) acc += s_rbf[(k << 5) + ii] * s_wk1[ii * HIDc + j];
        s_h[idx] = gelu_tanh(acc);
    }
    __syncthreads();

    // logits[k][h] = (h_vec . qk[:,h]) / sqrt(DH)
    {
        int k = tid >> 3, h = tid & 7;
        float acc = 0.0f;
        #pragma unroll 8
        for (int j = 0; j < HIDc; j++) acc += s_h[(k << 7) + j] * s_qk[(j << 3) + h];
        s_al[(k << 3) + h] = acc * 0.17677669529663687f;   // 1/sqrt(32)
    }
    __syncthreads();

    // cutoff-weighted softmax over k, per head
    if (tid < Hh) {
        int h = tid;
        float mx = -3.4e38f;
        for (int k = 0; k < Kk; k++) mx = fmaxf(mx, s_al[(k << 3) + h]);
        float sum = 0.0f;
        for (int k = 0; k < Kk; k++) {
            float w = s_cut[k] * expf(s_al[(k << 3) + h] - mx);
            s_al[(k << 3) + h] = w;
            sum += w;
        }
        float invs = 1.0f / (sum + 1e-9f);
        for (int k = 0; k < Kk; k++) s_al[(k << 3) + h] *= invs;
    }
    __syncthreads();

    // agg[d] = sum_k alpha[k,h(d)] * ( vn[src[k],d] + sh[k,:]@WvSh[:,d] )
    {
        int d = tid;
        int h = d >> 5;
        float wv[SHDc];
        #pragma unroll
        for (int s = 0; s < SHDc; s++) wv[s] = WvSh[s * Dd + d];
        const float* vnB = g_vn + (size_t)b * Nn * Dd;
        float acc = 0.0f;
        #pragma unroll 4
        for (int k = 0; k < Kk; k++) {
            float v = vnB[(size_t)s_id[k] * Dd + d];
            const float* shk = &s_shl[k * SHDc];
            #pragma unroll
            for (int s = 0; s < SHDc; s++) v += shk[s] * wv[s];
            acc += s_al[(k << 3) + h] * v;
        }
        g_agg[(size_t)m * Dd + d] = acc;
    }
}

// ---------------- final projection: out = agg @ Wo_out (256x3) ----------------
__global__ void final_kernel(const float* __restrict__ Wo_out, float* __restrict__ out) {
    int gid = blockIdx.x * blockDim.x + threadIdx.x;
    if (gid >= Mm * 3) return;
    int m = gid / 3, c = gid % 3;
    const float* a = g_agg + (size_t)m * Dd;
    float acc = 0.0f;
    #pragma unroll 8
    for (int j = 0; j < Dd; j++) acc += a[j] * Wo_out[j * 3 + c];
    out[gid] = acc;
}

// ---------------- host orchestration ----------------
extern "C" void kernel_launch(void* const* d_in, const int* in_sizes, int n_in,
                              void* d_out, int out_size) {
    const float* x       = (const float*)d_in[0];
    const float* y       = (const float*)d_in[1];
    const float* t       = (const float*)d_in[2];
    const float* W_embed = (const float*)d_in[3];
    const float* Wk1     = (const float*)d_in[4];
    const float* bk1     = (const float*)d_in[5];
    const float* Wk2     = (const float*)d_in[6];
    const float* Wq      = (const float*)d_in[7];
    const float* Wv      = (const float*)d_in[8];
    const float* Wo      = (const float*)d_in[9];
    const float* Wo_out  = (const float*)d_in[10];
    float* out = (float*)d_out;

    float *p_node, *p_q, *p_vn, *p_agg, *p_ssrc, *p_sdst, *p_qk;
    cudaGetSymbolAddress((void**)&p_node, g_node);
    cudaGetSymbolAddress((void**)&p_q,    g_q);
    cudaGetSymbolAddress((void**)&p_vn,   g_vn);
    cudaGetSymbolAddress((void**)&p_agg,  g_agg);
    cudaGetSymbolAddress((void**)&p_ssrc, g_ssrc);
    cudaGetSymbolAddress((void**)&p_sdst, g_sdst);
    cudaGetSymbolAddress((void**)&p_qk,   g_qk);

    knn_kernel<<<dim3(Nn / 256, Bb), 256>>>(x);
    geom_kernel<<<(Mm * Kk + 255) / 256, 256>>>(x);
    embed_kernel<<<Mm, Dd>>>(y, t, W_embed);
    tpart_kernel<<<Lc * Bb, HIDc>>>(t, Wk1, bk1);

    for (int l = 0; l < Lc; l++) {
        // q = node @ Wq[l]
        gemm_kernel<<<dim3(Mm / 64, Dd / 64), 256>>>(
            p_node, Dd, Wq + (size_t)l * Dd * Dd, Dd, 1,
            p_q, Dd, 1, Mm, Dd, Dd, nullptr, 0);
        // vn = node @ Wv[l][0:256,:]
        gemm_kernel<<<dim3(Mm / 64, Dd / 64), 256>>>(
            p_node, Dd, Wv + (size_t)l * (Dd + SHDc) * Dd, Dd, 1,
            p_vn, Dd, 1, Mm, Dd, Dd, nullptr, 0);
        // s_src = node[:, :128] @ Wk1[l][48:176]
        gemm_kernel<<<dim3(Mm / 64, HIDc / 64), 256>>>(
            p_node, Dd, Wk1 + ((size_t)l * EINc + 48) * HIDc, HIDc, 1,
            p_ssrc, HIDc, 1, Mm, HIDc, HIDc, nullptr, 0);
        // s_dst = node[:, :128] @ Wk1[l][176:304]
        gemm_kernel<<<dim3(Mm / 64, HIDc / 64), 256>>>(
            p_node, Dd, Wk1 + ((size_t)l * EINc + 176) * HIDc, HIDc, 1,
            p_sdst, HIDc, 1, Mm, HIDc, HIDc, nullptr, 0);
        // qk[m,j,h] = sum_d q[m,h*32+d] * Wk2[l][j][h*32+d]  (per-head GEMM)
        for (int h = 0; h < Hh; h++) {
            gemm_kernel<<<dim3(Mm / 64, HIDc / 64), 256>>>(
                p_q + h * DHh, Dd,
                Wk2 + (size_t)l * HIDc * Dd + h * DHh, 1, Dd,
                p_qk + h, HIDc * Hh, Hh, Mm, DHh, HIDc, nullptr, 0);
        }
        // fused edge MLP + attention + aggregation
        edge_kernel<<<Mm, 256>>>(Wk1, Wv, l);

        if (l < Lc - 1) {
            // node = act(node + agg @ Wo[l])
            gemm_kernel<<<dim3(Mm / 64, Dd / 64), 256>>>(
                p_agg, Dd, Wo + (size_t)l * Dd * Dd, Dd, 1,
                p_node, Dd, 1, Mm, Dd, Dd, p_node, 1);
        } else {
            final_kernel<<<(Mm * 3 + 255) / 256, 256>>>(Wo_out, out);
        }
    }
}

// round 3
// speedup vs baseline: 1.2580x; 1.2580x over previous
#include <cuda_runtime.h>
#include <math.h>

// ---------------- problem dims ----------------
#define Bb    8
#define Nn    1024
#define Kk    32
#define Dd    256
#define Hh    8
#define DHh   32
#define TDIMc 16
#define NBc   32
#define HIDc  128
#define Lc    4
#define NSc   128
#define SHDc  9
#define EINc  304
#define Mm    (Bb*Nn)

// ---------------- scratch (device globals; no allocs allowed) ----------------
__device__ int   g_src [Mm*Kk];
__device__ float g_r   [Mm*Kk];
__device__ float g_cutb[Mm*Kk];
__device__ float g_sh  [Mm*Kk*SHDc];
__device__ float g_node[Mm*Dd];
__device__ float g_qv  [Mm*512];        // [m][0:256]=q, [m][256:512]=vn
__device__ float g_ss  [Mm*256];        // [m][0:128]=ssrc, [m][128:256]=sdst
__device__ float g_agg [Mm*Dd];
__device__ float g_qk  [Mm*Hh*HIDc];    // [m][h][j]
__device__ float g_tpart[Lc*Bb*HIDc];
__device__ float g_wcat1[Lc*256*512];   // [l][k][ Wq | Wv_top ]
__device__ float g_wcat2[Lc*128*256];   // [l][k][ Wk1_src | Wk1_dst ]

__device__ __forceinline__ float gelu_tanh(float v) {
    float c = 0.7978845608028654f * (v + 0.044715f * v * v * v);
    return 0.5f * v * (1.0f + tanhf(c));
}

// ---------------- kNN: brute-force top-K smallest d2, stable tie-break ----------------
__global__ void knn_kernel(const float* __restrict__ x) {
    __shared__ float px[Nn], py[Nn], pz[Nn];
    int b = blockIdx.y;
    const float* xb = x + (size_t)b * Nn * 3;
    for (int i = threadIdx.x; i < Nn; i += blockDim.x) {
        px[i] = xb[i*3+0]; py[i] = xb[i*3+1]; pz[i] = xb[i*3+2];
    }
    __syncthreads();
    int n = blockIdx.x * blockDim.x + threadIdx.x;
    float qx = px[n], qy = py[n], qz = pz[n];
    float bd[Kk]; int bi[Kk];
    #pragma unroll
    for (int i = 0; i < Kk; i++) { bd[i] = 3.4e38f; bi[i] = 0x7fffffff; }
    for (int j = 0; j < Nn; j++) {
        float dx = qx - px[j], dy = qy - py[j], dz = qz - pz[j];
        float d2 = dx*dx + dy*dy + dz*dz;
        if (d2 < bd[Kk-1] || (d2 == bd[Kk-1] && j < bi[Kk-1])) {
            int p = Kk - 1;
            while (p > 0 && (bd[p-1] > d2 || (bd[p-1] == d2 && bi[p-1] > j))) {
                bd[p] = bd[p-1]; bi[p] = bi[p-1]; p--;
            }
            bd[p] = d2; bi[p] = j;
        }
    }
    int base = (b * Nn + n) * Kk;
    for (int i = 0; i < Kk; i++) g_src[base + i] = bi[i];
}

// ---------------- per-edge geometry: r, cutoff, spherical harmonics ----------------
__global__ void geom_kernel(const float* __restrict__ x) {
    int gid = blockIdx.x * blockDim.x + threadIdx.x;
    if (gid >= Mm * Kk) return;
    int m = gid / Kk;
    int b = m / Nn, n = m % Nn;
    int s = g_src[gid];
    const float* xb = x + (size_t)b * Nn * 3;
    float vx = xb[n*3+0] - xb[s*3+0];
    float vy = xb[n*3+1] - xb[s*3+1];
    float vz = xb[n*3+2] - xb[s*3+2];
    float r = sqrtf(vx*vx + vy*vy + vz*vz);
    g_r[gid] = r;
    float xc = 10.0f - 5.0f * r;                 // 10*(1 - r/2)
    g_cutb[gid] = (xc > 0.0f) ? 1.4f * expf(-1.0f / xc) : 0.0f;
    float inv = 1.0f / fmaxf(r, 1e-9f);
    float ux = vx * inv, uy = vy * inv, uz = vz * inv;
    const float s3 = 1.7320508075688772f;
    const float s15 = 3.872983346207417f;
    const float h5 = 1.118033988749895f;
    const float h15 = 1.9364916731037085f;
    float* sh = g_sh + (size_t)gid * SHDc;
    sh[0] = 1.0f;
    sh[1] = s3 * ux; sh[2] = s3 * uy; sh[3] = s3 * uz;
    sh[4] = s15 * ux * uy;
    sh[5] = s15 * uy * uz;
    sh[6] = h5 * (3.0f * uz * uz - 1.0f);
    sh[7] = s15 * ux * uz;
    sh[8] = h15 * (ux * ux - uy * uy);
}

// ---------------- node embedding: [y,t] @ W_embed (19x256) ----------------
__global__ void embed_kernel(const float* __restrict__ y, const float* __restrict__ t,
                             const float* __restrict__ W_embed) {
    __shared__ float in[3 + TDIMc];
    int m = blockIdx.x;
    int b = m / Nn;
    int tid = threadIdx.x;
    if (tid < 3) in[tid] = y[(size_t)m * 3 + tid];
    else if (tid < 3 + TDIMc) in[tid] = t[b * TDIMc + (tid - 3)];
    __syncthreads();
    float acc = 0.0f;
    #pragma unroll
    for (int i = 0; i < 3 + TDIMc; i++) acc += in[i] * W_embed[i * Dd + tid];
    g_node[(size_t)m * Dd + tid] = acc;
}

// ---------------- tpart[l][b][j] = bk1[l][j] + t[b]@Wk1[l][32:48][j] ----------------
__global__ void tpart_kernel(const float* __restrict__ t, const float* __restrict__ Wk1,
                             const float* __restrict__ bk1) {
    int l = blockIdx.x / Bb, b = blockIdx.x % Bb;
    int j = threadIdx.x;
    float acc = bk1[l * HIDc + j];
    #pragma unroll
    for (int i = 0; i < TDIMc; i++)
        acc += t[b * TDIMc + i] * Wk1[((size_t)l * EINc + 32 + i) * HIDc + j];
    g_tpart[(l * Bb + b) * HIDc + j] = acc;
}

// ---------------- pack weights: wcat1 = [Wq | Wv_top], wcat2 = [Wk1_src | Wk1_dst] ----
__global__ void pack_kernel(const float* __restrict__ Wq, const float* __restrict__ Wv,
                            const float* __restrict__ Wk1) {
    int i = blockIdx.x * 256 + threadIdx.x;
    const int SZ1 = Lc * 256 * 512;
    if (i < SZ1) {
        int l = i / (256 * 512);
        int r = (i >> 9) & 255;
        int n = i & 511;
        float v = (n < 256) ? Wq[((size_t)l * 256 + r) * 256 + n]
                            : Wv[((size_t)l * (Dd + SHDc) + r) * 256 + (n - 256)];
        g_wcat1[i] = v;
    } else {
        int j = i - SZ1;                      // Lc*128*256
        int l = j / (128 * 256);
        int r = (j >> 8) & 127;
        int n = j & 255;
        int row = (n < 128) ? (48 + r) : (176 + r);
        g_wcat2[j] = Wk1[((size_t)l * EINc + row) * HIDc + (n & 127)];
    }
}

// ---------------- SGEMM 128x64 tile, 8x4/thread, float4 smem ----------------
// C[m*ldc+n] = sum_k A[m*lda+k] * W[k*ldw+n]  (+ residual/activation)
// actmode 1: v = resid + acc; n<64 gelu, 64<=n<128 tanh, else id.
__global__ void gemm128(const float* __restrict__ A, int lda,
                        const float* __restrict__ W, int ldw,
                        float* __restrict__ C, int ldc, int Kd,
                        const float* __restrict__ resid, int actmode) {
    __shared__ float As[16][132];   // [kk][m]
    __shared__ float Ws[16][68];    // [kk][n]
    int m0 = blockIdx.x * 128, n0 = blockIdx.y * 64;
    int tid = threadIdx.x;
    int tx = tid & 15, ty = tid >> 4;
    float acc[8][4];
    #pragma unroll
    for (int i = 0; i < 8; i++)
        #pragma unroll
        for (int j = 0; j < 4; j++) acc[i][j] = 0.0f;

    for (int k0 = 0; k0 < Kd; k0 += 16) {
        #pragma unroll
        for (int u = 0; u < 2; u++) {
            int id = tid * 2 + u;                 // 0..511 float4s
            int row = id >> 2, c4 = (id & 3) * 4;
            float4 v = *(const float4*)&A[(size_t)(m0 + row) * lda + k0 + c4];
            As[c4 + 0][row] = v.x; As[c4 + 1][row] = v.y;
            As[c4 + 2][row] = v.z; As[c4 + 3][row] = v.w;
        }
        {
            int row = tid >> 4, c4 = (tid & 15) * 4;
            float4 v = *(const float4*)&W[(size_t)(k0 + row) * ldw + n0 + c4];
            *(float4*)&Ws[row][c4] = v;
        }
        __syncthreads();
        #pragma unroll
        for (int kk = 0; kk < 16; kk++) {
            float4 a0 = *(const float4*)&As[kk][ty * 8];
            float4 a1 = *(const float4*)&As[kk][ty * 8 + 4];
            float4 bv = *(const float4*)&Ws[kk][tx * 4];
            float am[8] = {a0.x, a0.y, a0.z, a0.w, a1.x, a1.y, a1.z, a1.w};
            float bm[4] = {bv.x, bv.y, bv.z, bv.w};
            #pragma unroll
            for (int i = 0; i < 8; i++)
                #pragma unroll
                for (int j = 0; j < 4; j++) acc[i][j] += am[i] * bm[j];
        }
        __syncthreads();
    }
    #pragma unroll
    for (int i = 0; i < 8; i++) {
        int mrow = m0 + ty * 8 + i;
        #pragma unroll
        for (int j = 0; j < 4; j++) {
            int n = n0 + tx * 4 + j;
            float v = acc[i][j];
            if (actmode == 1) {
                v += resid[(size_t)mrow * ldc + n];
                if (n < 64) v = gelu_tanh(v);
                else if (n < 128) v = tanhf(v);
            }
            C[(size_t)mrow * ldc + n] = v;
        }
    }
}

// ---------------- batched per-head qk GEMM: qk[m][h][j] = q[m,h,:]·Wk2[j,h,:] -------
__global__ void qk_kernel(const float* __restrict__ Wk2, int l) {
    __shared__ float qsT[32 * 68];    // [d][m]
    __shared__ float wsT[32 * 132];   // [d][j]
    int m0 = blockIdx.x * 64;
    int h = blockIdx.y;
    int tid = threadIdx.x;
    const float* W = Wk2 + (size_t)l * HIDc * Dd;
    #pragma unroll
    for (int u = 0; u < 2; u++) {
        int id = tid * 2 + u;                 // 0..511 f4: 64 rows x 8 f4
        int row = id >> 3, c4 = (id & 7) * 4;
        float4 v = *(const float4*)&g_qv[(size_t)(m0 + row) * 512 + h * 32 + c4];
        qsT[(c4 + 0) * 68 + row] = v.x; qsT[(c4 + 1) * 68 + row] = v.y;
        qsT[(c4 + 2) * 68 + row] = v.z; qsT[(c4 + 3) * 68 + row] = v.w;
    }
    #pragma unroll
    for (int u = 0; u < 4; u++) {
        int id = tid * 4 + u;                 // 0..1023 f4: 128 rows x 8 f4
        int j = id >> 3, c4 = (id & 7) * 4;
        float4 v = *(const float4*)&W[(size_t)j * 256 + h * 32 + c4];
        wsT[(c4 + 0) * 132 + j] = v.x; wsT[(c4 + 1) * 132 + j] = v.y;
        wsT[(c4 + 2) * 132 + j] = v.z; wsT[(c4 + 3) * 132 + j] = v.w;
    }
    __syncthreads();
    int tx = tid & 31, ty = tid >> 5;         // j0 = tx*4, m-block = ty*8
    float acc[8][4];
    #pragma unroll
    for (int i = 0; i < 8; i++)
        #pragma unroll
        for (int j = 0; j < 4; j++) acc[i][j] = 0.0f;
    #pragma unroll
    for (int d = 0; d < 32; d++) {
        float4 a0 = *(const float4*)&qsT[d * 68 + ty * 8];
        float4 a1 = *(const float4*)&qsT[d * 68 + ty * 8 + 4];
        float4 bv = *(const float4*)&wsT[d * 132 + tx * 4];
        float am[8] = {a0.x, a0.y, a0.z, a0.w, a1.x, a1.y, a1.z, a1.w};
        float bm[4] = {bv.x, bv.y, bv.z, bv.w};
        #pragma unroll
        for (int i = 0; i < 8; i++)
            #pragma unroll
            for (int j = 0; j < 4; j++) acc[i][j] += am[i] * bm[j];
    }
    #pragma unroll
    for (int i = 0; i < 8; i++) {
        float4 o = make_float4(acc[i][0], acc[i][1], acc[i][2], acc[i][3]);
        *(float4*)&g_qk[(size_t)(m0 + ty * 8 + i) * 1024 + h * 128 + tx * 4] = o;
    }
}

// ---------------- fused per-node edge/attention kernel (one block per node) --------
__global__ void edge_kernel(const float* __restrict__ Wk1, const float* __restrict__ Wv,
                            int l) {
    __shared__ float s_wk1[32 * 128];   // [ii][j]
    __shared__ float s_h  [32 * 128];   // [k][j]
    __shared__ float s_rbfT[32 * 36];   // [ii][k]
    __shared__ float s_qk [8 * 132];    // [h][j]
    __shared__ float s_al [32 * 8];     // [k][h]
    __shared__ float s_part[32 * 8 * 2];
    __shared__ float s_shl[32 * 9];     // [k][s]
    __shared__ float s_base[128];
    __shared__ float s_r[32], s_cut[32];
    __shared__ int   s_id[32];

    int m = blockIdx.x;
    int b = m / Nn;
    int tid = threadIdx.x;
    const float* Wk1l = Wk1 + (size_t)l * EINc * HIDc;          // rows 0..31 = rbf part
    const float* WvSh = Wv + ((size_t)l * (Dd + SHDc) + Dd) * Dd;
    const float* tpl  = g_tpart + (l * Bb + b) * HIDc;

    if (tid < 32) {
        s_id[tid]  = g_src [m * 32 + tid];
        s_r[tid]   = g_r   [m * 32 + tid];
        s_cut[tid] = g_cutb[m * 32 + tid];
    }
    if (tid < 128) s_base[tid] = g_ss[(size_t)m * 256 + 128 + tid] + tpl[tid];
    for (int i = tid; i < 1024; i += 256) {
        int h = i >> 7, j = i & 127;
        s_qk[h * 132 + j] = g_qk[(size_t)m * 1024 + i];
    }
    for (int i = tid; i < 32 * SHDc; i += 256) s_shl[i] = g_sh[(size_t)m * 32 * SHDc + i];
    for (int i = tid; i < 4096; i += 256) s_wk1[i] = Wk1l[i];
    __syncthreads();

    // rbf (transposed [ii][k]), gaussian * cutoff
    const float ISTEP = 15.5f;
    const float RBFC  = 5.656854249492381f * 0.95f / 1.12f;
    for (int i = tid; i < 1024; i += 256) {
        int ii = i >> 5, k = i & 31;
        float d = s_r[k] * ISTEP - (float)ii;
        s_rbfT[ii * 36 + k] = expf(-d * d) * RBFC * s_cut[k];
    }
    __syncthreads();

    // h-MLP: 32k x 128j x 32ii outer-product, 4x4 per thread
    {
        int tx = tid & 31, ty = tid >> 5;
        int j0 = tx * 4, k0 = ty * 4;
        float acc[4][4];
        #pragma unroll
        for (int i = 0; i < 4; i++)
            #pragma unroll
            for (int j = 0; j < 4; j++) acc[i][j] = 0.0f;
        #pragma unroll
        for (int ii = 0; ii < 32; ii++) {
            float4 rb = *(const float4*)&s_rbfT[ii * 36 + k0];
            float4 wv4 = *(const float4*)&s_wk1[ii * 128 + j0];
            float rr[4] = {rb.x, rb.y, rb.z, rb.w};
            float ww[4] = {wv4.x, wv4.y, wv4.z, wv4.w};
            #pragma unroll
            for (int ki = 0; ki < 4; ki++)
                #pragma unroll
                for (int ji = 0; ji < 4; ji++) acc[ki][ji] += rr[ki] * ww[ji];
        }
        const float* ssB = g_ss + (size_t)b * Nn * 256;
        float4 base = *(const float4*)&s_base[j0];
        #pragma unroll
        for (int ki = 0; ki < 4; ki++) {
            int k = k0 + ki;
            float4 sv = *(const float4*)&ssB[(size_t)s_id[k] * 256 + j0];
            float4 o;
            o.x = gelu_tanh(acc[ki][0] + sv.x + base.x);
            o.y = gelu_tanh(acc[ki][1] + sv.y + base.y);
            o.z = gelu_tanh(acc[ki][2] + sv.z + base.z);
            o.w = gelu_tanh(acc[ki][3] + sv.w + base.w);
            *(float4*)&s_h[k * 128 + j0] = o;
        }
    }
    __syncthreads();

    // logits partials: (k x head-pair x j-half)
    {
        int k = tid >> 3, r = tid & 7, hp = r >> 1, s = r & 1;
        int h0 = hp * 2, h1 = h0 + 1, jb = s * 64;
        float a0 = 0.0f, a1 = 0.0f;
        #pragma unroll
        for (int j = jb; j < jb + 64; j += 4) {
            float4 hv = *(const float4*)&s_h[k * 128 + j];
            float4 q0 = *(const float4*)&s_qk[h0 * 132 + j];
            float4 q1 = *(const float4*)&s_qk[h1 * 132 + j];
            a0 += hv.x*q0.x + hv.y*q0.y + hv.z*q0.z + hv.w*q0.w;
            a1 += hv.x*q1.x + hv.y*q1.y + hv.z*q1.z + hv.w*q1.w;
        }
        s_part[(k * 8 + h0) * 2 + s] = a0;
        s_part[(k * 8 + h1) * 2 + s] = a1;
    }
    __syncthreads();
    {
        int k = tid >> 3, h = tid & 7;
        s_al[k * 8 + h] = (s_part[(k * 8 + h) * 2] + s_part[(k * 8 + h) * 2 + 1])
                          * 0.17677669529663687f;   // 1/sqrt(32)
    }
    __syncthreads();

    // cutoff-weighted softmax over k, per head
    if (tid < Hh) {
        int h = tid;
        float mx = -3.4e38f;
        for (int k = 0; k < 32; k++) mx = fmaxf(mx, s_al[k * 8 + h]);
        float sum = 0.0f;
        for (int k = 0; k < 32; k++) {
            float w = s_cut[k] * expf(s_al[k * 8 + h] - mx);
            s_al[k * 8 + h] = w;
            sum += w;
        }
        float invs = 1.0f / (sum + 1e-9f);
        for (int k = 0; k < 32; k++) s_al[k * 8 + h] *= invs;
    }
    __syncthreads();

    // agg[d] = sum_k alpha[k,h(d)] * ( vn[src[k],d] + sh[k,:]@WvSh[:,d] )
    {
        int d = tid;
        int h = d >> 5;
        float wv[SHDc];
        #pragma unroll
        for (int s = 0; s < SHDc; s++) wv[s] = WvSh[s * Dd + d];
        const float* vnB = g_qv + (size_t)b * Nn * 512 + 256;
        float acc = 0.0f;
        #pragma unroll 4
        for (int k = 0; k < 32; k++) {
            float v = vnB[(size_t)s_id[k] * 512 + d];
            const float* shk = &s_shl[k * SHDc];
            #pragma unroll
            for (int s = 0; s < SHDc; s++) v += shk[s] * wv[s];
            acc += s_al[k * 8 + h] * v;
        }
        g_agg[(size_t)m * Dd + d] = acc;
    }
}

// ---------------- final projection: out = agg @ Wo_out (256x3) ----------------
__global__ void final_kernel(const float* __restrict__ Wo_out, float* __restrict__ out) {
    int gid = blockIdx.x * blockDim.x + threadIdx.x;
    if (gid >= Mm * 3) return;
    int m = gid / 3, c = gid % 3;
    const float* a = g_agg + (size_t)m * Dd;
    float acc = 0.0f;
    #pragma unroll 8
    for (int j = 0; j < Dd; j++) acc += a[j] * Wo_out[j * 3 + c];
    out[gid] = acc;
}

// ---------------- host orchestration ----------------
extern "C" void kernel_launch(void* const* d_in, const int* in_sizes, int n_in,
                              void* d_out, int out_size) {
    const float* x       = (const float*)d_in[0];
    const float* y       = (const float*)d_in[1];
    const float* t       = (const float*)d_in[2];
    const float* W_embed = (const float*)d_in[3];
    const float* Wk1     = (const float*)d_in[4];
    const float* bk1     = (const float*)d_in[5];
    const float* Wk2     = (const float*)d_in[6];
    const float* Wq      = (const float*)d_in[7];
    const float* Wv      = (const float*)d_in[8];
    const float* Wo      = (const float*)d_in[9];
    const float* Wo_out  = (const float*)d_in[10];
    float* out = (float*)d_out;

    float *p_node, *p_qv, *p_ss, *p_agg, *p_wcat1, *p_wcat2;
    cudaGetSymbolAddress((void**)&p_node,  g_node);
    cudaGetSymbolAddress((void**)&p_qv,    g_qv);
    cudaGetSymbolAddress((void**)&p_ss,    g_ss);
    cudaGetSymbolAddress((void**)&p_agg,   g_agg);
    cudaGetSymbolAddress((void**)&p_wcat1, g_wcat1);
    cudaGetSymbolAddress((void**)&p_wcat2, g_wcat2);

    knn_kernel<<<dim3(Nn / 256, Bb), 256>>>(x);
    geom_kernel<<<(Mm * Kk + 255) / 256, 256>>>(x);
    embed_kernel<<<Mm, Dd>>>(y, t, W_embed);
    tpart_kernel<<<Lc * Bb, HIDc>>>(t, Wk1, bk1);
    pack_kernel<<<(Lc * 256 * 512 + Lc * 128 * 256) / 256, 256>>>(Wq, Wv, Wk1);

    for (int l = 0; l < Lc; l++) {
        // [q | vn] = node @ wcat1[l]   (8192 x 512 x 256)
        gemm128<<<dim3(Mm / 128, 512 / 64), 256>>>(
            p_node, Dd, p_wcat1 + (size_t)l * 256 * 512, 512,
            p_qv, 512, 256, nullptr, 0);
        // [ssrc | sdst] = node[:, :128] @ wcat2[l]   (8192 x 256 x 128)
        gemm128<<<dim3(Mm / 128, 256 / 64), 256>>>(
            p_node, Dd, p_wcat2 + (size_t)l * 128 * 256, 256,
            p_ss, 256, 128, nullptr, 0);
        // qk[m][h][j] batched over heads
        qk_kernel<<<dim3(Mm / 64, Hh), 256>>>(Wk2, l);
        // fused edge MLP + attention + aggregation
        edge_kernel<<<Mm, 256>>>(Wk1, Wv, l);

        if (l < Lc - 1) {
            // node = act(node + agg @ Wo[l])
            gemm128<<<dim3(Mm / 128, 256 / 64), 256>>>(
                p_agg, Dd, Wo + (size_t)l * Dd * Dd, Dd,
                p_node, Dd, 256, p_node, 1);
        } else {
            final_kernel<<<(Mm * 3 + 255) / 256, 256>>>(Wo_out, out);
        }
    }
}

// round 5
// speedup vs baseline: 2.8986x; 2.3041x over previous
#include <cuda_runtime.h>
#include <math.h>

// ---------------- problem dims ----------------
#define Bb    8
#define Nn    1024
#define Kk    32
#define Dd    256
#define Hh    8
#define DHh   32
#define TDIMc 16
#define NBc   32
#define HIDc  128
#define Lc    4
#define NSc   128
#define SHDc  9
#define EINc  304
#define Mm    (Bb*Nn)

// ---------------- scratch (device globals; no allocs allowed) ----------------
__device__ int   g_src [Mm*Kk];
__device__ float g_cutb[Mm*Kk];
__device__ float g_sh  [Mm*Kk*SHDc];
__device__ float g_rbf [Mm*Kk*NBc];     // rbf*cut, layer-invariant (32 MB)
__device__ float g_node[Mm*Dd];
__device__ float g_qv  [Mm*512];        // [m][0:256]=q, [m][256:512]=vn
__device__ float g_ss  [Mm*256];        // [m][0:128]=ssrc, [m][128:256]=sdst
__device__ float g_agg [Mm*Dd];
__device__ float g_qk  [Mm*Hh*HIDc];    // [m][h][j]
__device__ float g_tpart[Lc*Bb*HIDc];
__device__ float g_wcat1[Lc*256*512];   // [l][k][ Wq | Wv_top ]
__device__ float g_wcat2[Lc*128*256];   // [l][k][ Wk1_src | Wk1_dst ]

// ---------------- FFMA-only fast math (no MUFU in hot paths) ----------------
__device__ __forceinline__ float fast_rcp(float q) {
    float r = __int_as_float(0x7EF311C3 - __float_as_int(q));
    r = r * (2.0f - q * r);
    r = r * (2.0f - q * r);
    r = r * (2.0f - q * r);
    return r;
}
__device__ __forceinline__ float tanh_fast(float x) {
    x = fminf(fmaxf(x, -7.90531110591f), 7.90531110591f);
    float x2 = x * x;
    float p = fmaf(x2, -2.76076847742355e-16f, 2.00018790482477e-13f);
    p = fmaf(x2, p, -8.60467152213735e-11f);
    p = fmaf(x2, p,  5.12229709037114e-08f);
    p = fmaf(x2, p,  1.48572235717979e-05f);
    p = fmaf(x2, p,  6.37261928875436e-04f);
    p = fmaf(x2, p,  4.89352455891786e-03f);
    p = p * x;
    float q = fmaf(x2, 1.19825839466702e-06f, 1.18534705686654e-04f);
    q = fmaf(x2, q, 2.26843463243900e-03f);
    q = fmaf(x2, q, 4.89352518554385e-03f);
    return p * fast_rcp(q);
}
__device__ __forceinline__ float gelu_fast(float v) {
    float c = v * fmaf(v * v, 0.0356774081363f, 0.7978845608028654f);
    return 0.5f * v * (1.0f + tanh_fast(c));
}
__device__ __forceinline__ float exp_fast(float x) {   // expects x <= 0
    x = fmaxf(x, -80.0f);
    float y = x * 1.4426950408889634f;
    float n = floorf(y);
    float f = y - n;
    float p = 1.5252733804059838e-5f;
    p = fmaf(p, f, 1.5403530393381606e-4f);
    p = fmaf(p, f, 1.3333558146428443e-3f);
    p = fmaf(p, f, 9.618129107628477e-3f);
    p = fmaf(p, f, 5.550410866482158e-2f);
    p = fmaf(p, f, 2.402265069591007e-1f);
    p = fmaf(p, f, 6.931471805599453e-1f);
    p = fmaf(p, f, 1.0f);
    return p * __int_as_float(((int)n + 127) << 23);
}

// ---------------- warp-collective kNN: lane-held top-32, unsorted ----------------
__global__ void knn_kernel(const float* __restrict__ x) {
    __shared__ float px[Nn], py[Nn], pz[Nn];
    int b = blockIdx.y;
    const float* xb = x + (size_t)b * Nn * 3;
    for (int i = threadIdx.x; i < Nn; i += blockDim.x) {
        px[i] = xb[i*3+0]; py[i] = xb[i*3+1]; pz[i] = xb[i*3+2];
    }
    __syncthreads();
    int warp = threadIdx.x >> 5, lane = threadIdx.x & 31;
    int n = blockIdx.x * 8 + warp;
    float qx = px[n], qy = py[n], qz = pz[n];

    // init with candidates 0..31
    float dx = qx - px[lane], dy = qy - py[lane], dz = qz - pz[lane];
    float best_d = dx*dx + dy*dy + dz*dz;
    int   best_i = lane;
    // thr = current warp max of best_d
    float thr = best_d;
    #pragma unroll
    for (int off = 16; off; off >>= 1) thr = fmaxf(thr, __shfl_xor_sync(~0u, thr, off));

    for (int j0 = 32; j0 < Nn; j0 += 32) {
        int j = j0 + lane;
        dx = qx - px[j]; dy = qy - py[j]; dz = qz - pz[j];
        float d2 = dx*dx + dy*dy + dz*dz;
        unsigned mask = __ballot_sync(~0u, d2 < thr);
        while (mask) {
            int src = __ffs(mask) - 1; mask &= mask - 1;
            float cd = __shfl_sync(~0u, d2, src);
            int   ci = j0 + src;
            // warp argmax of best_d
            float m = best_d; int ml = lane;
            #pragma unroll
            for (int off = 16; off; off >>= 1) {
                float om = __shfl_xor_sync(~0u, m, off);
                int  oml = __shfl_xor_sync(~0u, ml, off);
                if (om > m || (om == m && oml > ml)) { m = om; ml = oml; }
            }
            if (cd < m) {
                if (lane == ml) { best_d = cd; best_i = ci; }
            }
            thr = m;   // safe (>= true max)
        }
    }
    g_src[(b * Nn + n) * Kk + lane] = best_i;
}

// ---------------- per-edge geometry: cutoff, sh, rbf*cut (precomputed) ----------------
__global__ void geom_kernel(const float* __restrict__ x) {
    int gid = blockIdx.x * blockDim.x + threadIdx.x;
    if (gid >= Mm * Kk) return;
    int m = gid / Kk;
    int b = m / Nn, n = m % Nn;
    int s = g_src[gid];
    const float* xb = x + (size_t)b * Nn * 3;
    float vx = xb[n*3+0] - xb[s*3+0];
    float vy = xb[n*3+1] - xb[s*3+1];
    float vz = xb[n*3+2] - xb[s*3+2];
    float r = sqrtf(vx*vx + vy*vy + vz*vz);
    float xc = 10.0f - 5.0f * r;
    float cut = (xc > 0.0f) ? 1.4f * exp_fast(-fast_rcp(xc)) : 0.0f;
    g_cutb[gid] = cut;
    float inv = 1.0f / fmaxf(r, 1e-9f);
    float ux = vx * inv, uy = vy * inv, uz = vz * inv;
    const float s3 = 1.7320508075688772f;
    const float s15 = 3.872983346207417f;
    const float h5 = 1.118033988749895f;
    const float h15 = 1.9364916731037085f;
    float* sh = g_sh + (size_t)gid * SHDc;
    sh[0] = 1.0f;
    sh[1] = s3 * ux; sh[2] = s3 * uy; sh[3] = s3 * uz;
    sh[4] = s15 * ux * uy;
    sh[5] = s15 * uy * uz;
    sh[6] = h5 * (3.0f * uz * uz - 1.0f);
    sh[7] = s15 * ux * uz;
    sh[8] = h15 * (ux * ux - uy * uy);
    // rbf * cut (layer-invariant)
    const float ISTEP = 15.5f;
    const float RBFC  = 5.656854249492381f * 0.95f / 1.12f;
    float base = r * ISTEP;
    float rb[NBc];
    #pragma unroll
    for (int ii = 0; ii < NBc; ii++) {
        float d = base - (float)ii;
        rb[ii] = exp_fast(-d * d) * RBFC * cut;
    }
    float4* dst = (float4*)(g_rbf + (size_t)gid * NBc);
    #pragma unroll
    for (int u = 0; u < 8; u++)
        dst[u] = make_float4(rb[u*4], rb[u*4+1], rb[u*4+2], rb[u*4+3]);
}

// ---------------- node embedding: [y,t] @ W_embed (19x256) ----------------
__global__ void embed_kernel(const float* __restrict__ y, const float* __restrict__ t,
                             const float* __restrict__ W_embed) {
    __shared__ float in[3 + TDIMc];
    int m = blockIdx.x;
    int b = m / Nn;
    int tid = threadIdx.x;
    if (tid < 3) in[tid] = y[(size_t)m * 3 + tid];
    else if (tid < 3 + TDIMc) in[tid] = t[b * TDIMc + (tid - 3)];
    __syncthreads();
    float acc = 0.0f;
    #pragma unroll
    for (int i = 0; i < 3 + TDIMc; i++) acc += in[i] * W_embed[i * Dd + tid];
    g_node[(size_t)m * Dd + tid] = acc;
}

// ---------------- tpart[l][b][j] = bk1[l][j] + t[b]@Wk1[l][32:48][j] ----------------
__global__ void tpart_kernel(const float* __restrict__ t, const float* __restrict__ Wk1,
                             const float* __restrict__ bk1) {
    int l = blockIdx.x / Bb, b = blockIdx.x % Bb;
    int j = threadIdx.x;
    float acc = bk1[l * HIDc + j];
    #pragma unroll
    for (int i = 0; i < TDIMc; i++)
        acc += t[b * TDIMc + i] * Wk1[((size_t)l * EINc + 32 + i) * HIDc + j];
    g_tpart[(l * Bb + b) * HIDc + j] = acc;
}

// ---------------- pack weights ----------------
__global__ void pack_kernel(const float* __restrict__ Wq, const float* __restrict__ Wv,
                            const float* __restrict__ Wk1) {
    int i = blockIdx.x * 256 + threadIdx.x;
    const int SZ1 = Lc * 256 * 512;
    if (i < SZ1) {
        int l = i / (256 * 512);
        int r = (i >> 9) & 255;
        int n = i & 511;
        float v = (n < 256) ? Wq[((size_t)l * 256 + r) * 256 + n]
                            : Wv[((size_t)l * (Dd + SHDc) + r) * 256 + (n - 256)];
        g_wcat1[i] = v;
    } else {
        int j = i - SZ1;
        int l = j / (128 * 256);
        int r = (j >> 8) & 127;
        int n = j & 255;
        int row = (n < 128) ? (48 + r) : (176 + r);
        g_wcat2[j] = Wk1[((size_t)l * EINc + row) * HIDc + (n & 127)];
    }
}

// ---------------- SGEMM 128x128 tile, 8x8/thread (LDS:FMA balanced) ----------------
__global__ void gemm_big(const float* __restrict__ A, int lda,
                         const float* __restrict__ W, int ldw,
                         float* __restrict__ C, int ldc, int Kd,
                         const float* __restrict__ resid, int actmode) {
    __shared__ float As[16][132];
    __shared__ float Ws[16][132];
    int m0 = blockIdx.x * 128, n0 = blockIdx.y * 128;
    int tid = threadIdx.x;
    int tx = tid & 15, ty = tid >> 4;
    float acc[8][8];
    #pragma unroll
    for (int i = 0; i < 8; i++)
        #pragma unroll
        for (int j = 0; j < 8; j++) acc[i][j] = 0.0f;

    for (int k0 = 0; k0 < Kd; k0 += 16) {
        #pragma unroll
        for (int u = 0; u < 2; u++) {
            int id = tid * 2 + u;                 // 512 f4 = 128 rows x 4 f4
            int row = id >> 2, c4 = (id & 3) * 4;
            float4 v = *(const float4*)&A[(size_t)(m0 + row) * lda + k0 + c4];
            As[c4 + 0][row] = v.x; As[c4 + 1][row] = v.y;
            As[c4 + 2][row] = v.z; As[c4 + 3][row] = v.w;
        }
        #pragma unroll
        for (int u = 0; u < 2; u++) {
            int id = tid * 2 + u;                 // 512 f4 = 16 rows x 32 f4
            int row = id >> 5, c4 = (id & 31) * 4;
            float4 v = *(const float4*)&W[(size_t)(k0 + row) * ldw + n0 + c4];
            *(float4*)&Ws[row][c4] = v;
        }
        __syncthreads();
        #pragma unroll
        for (int kk = 0; kk < 16; kk++) {
            float a[8], bw[8];
            *(float4*)&a[0]  = *(const float4*)&As[kk][ty * 8];
            *(float4*)&a[4]  = *(const float4*)&As[kk][ty * 8 + 4];
            *(float4*)&bw[0] = *(const float4*)&Ws[kk][tx * 8];
            *(float4*)&bw[4] = *(const float4*)&Ws[kk][tx * 8 + 4];
            #pragma unroll
            for (int i = 0; i < 8; i++)
                #pragma unroll
                for (int j = 0; j < 8; j++) acc[i][j] += a[i] * bw[j];
        }
        __syncthreads();
    }
    #pragma unroll
    for (int i = 0; i < 8; i++) {
        int mrow = m0 + ty * 8 + i;
        #pragma unroll
        for (int j = 0; j < 8; j++) {
            int n = n0 + tx * 8 + j;
            float v = acc[i][j];
            if (actmode == 1) {
                v += resid[(size_t)mrow * ldc + n];
                if (n < 64) v = gelu_fast(v);
                else if (n < 128) v = tanh_fast(v);
            }
            C[(size_t)mrow * ldc + n] = v;
        }
    }
}

// ---------------- batched per-head qk GEMM: qk[m][h][j] = q[m,h,:]·Wk2[j,h,:] -------
__global__ void qk_kernel(const float* __restrict__ Wk2, int l) {
    __shared__ float qsT[32 * 68];    // [d][m]
    __shared__ float wsT[32 * 132];   // [d][j]
    int m0 = blockIdx.x * 64;
    int h = blockIdx.y;
    int tid = threadIdx.x;
    const float* W = Wk2 + (size_t)l * HIDc * Dd;
    #pragma unroll
    for (int u = 0; u < 2; u++) {
        int id = tid * 2 + u;
        int row = id >> 3, c4 = (id & 7) * 4;
        float4 v = *(const float4*)&g_qv[(size_t)(m0 + row) * 512 + h * 32 + c4];
        qsT[(c4 + 0) * 68 + row] = v.x; qsT[(c4 + 1) * 68 + row] = v.y;
        qsT[(c4 + 2) * 68 + row] = v.z; qsT[(c4 + 3) * 68 + row] = v.w;
    }
    #pragma unroll
    for (int u = 0; u < 4; u++) {
        int id = tid * 4 + u;
        int j = id >> 3, c4 = (id & 7) * 4;
        float4 v = *(const float4*)&W[(size_t)j * 256 + h * 32 + c4];
        wsT[(c4 + 0) * 132 + j] = v.x; wsT[(c4 + 1) * 132 + j] = v.y;
        wsT[(c4 + 2) * 132 + j] = v.z; wsT[(c4 + 3) * 132 + j] = v.w;
    }
    __syncthreads();
    int tx = tid & 31, ty = tid >> 5;
    float acc[8][4];
    #pragma unroll
    for (int i = 0; i < 8; i++)
        #pragma unroll
        for (int j = 0; j < 4; j++) acc[i][j] = 0.0f;
    #pragma unroll
    for (int d = 0; d < 32; d++) {
        float4 a0 = *(const float4*)&qsT[d * 68 + ty * 8];
        float4 a1 = *(const float4*)&qsT[d * 68 + ty * 8 + 4];
        float4 bv = *(const float4*)&wsT[d * 132 + tx * 4];
        float am[8] = {a0.x, a0.y, a0.z, a0.w, a1.x, a1.y, a1.z, a1.w};
        float bm[4] = {bv.x, bv.y, bv.z, bv.w};
        #pragma unroll
        for (int i = 0; i < 8; i++)
            #pragma unroll
            for (int j = 0; j < 4; j++) acc[i][j] += am[i] * bm[j];
    }
    #pragma unroll
    for (int i = 0; i < 8; i++) {
        float4 o = make_float4(acc[i][0], acc[i][1], acc[i][2], acc[i][3]);
        *(float4*)&g_qk[(size_t)(m0 + ty * 8 + i) * 1024 + h * 128 + tx * 4] = o;
    }
}

// ---------------- fused edge kernel: hMLP+gelu+logits in regs, butterfly reduce ----
__global__ void edge_kernel(const float* __restrict__ Wk1, const float* __restrict__ Wv,
                            int l) {
    __shared__ float s_wk1[32 * 128];   // [ii][j]
    __shared__ float s_rbfT[32 * 36];   // [ii][k]
    __shared__ float s_qk [8 * 132];    // [h][j]
    __shared__ float s_al [32 * 8];     // [k][h]
    __shared__ float s_shl[32 * 9];     // [k][s]
    __shared__ float s_base[128];
    __shared__ float s_cut[32];
    __shared__ int   s_id[32];

    int m = blockIdx.x;
    int b = m >> 10;
    int tid = threadIdx.x;
    const float* Wk1l = Wk1 + (size_t)l * EINc * HIDc;
    const float* WvSh = Wv + ((size_t)l * (Dd + SHDc) + Dd) * Dd;
    const float* tpl  = g_tpart + (l * Bb + b) * HIDc;

    if (tid < 32) {
        s_id[tid]  = g_src [m * 32 + tid];
        s_cut[tid] = g_cutb[m * 32 + tid];
    }
    if (tid < 128) s_base[tid] = g_ss[(size_t)m * 256 + 128 + tid] + tpl[tid];
    for (int i = tid; i < 1024; i += 256) {
        int h = i >> 7, j = i & 127;
        s_qk[h * 132 + j] = g_qk[(size_t)m * 1024 + i];
    }
    for (int i = tid; i < 32 * SHDc; i += 256) s_shl[i] = g_sh[(size_t)m * 32 * SHDc + i];
    {   // rbf load + transpose: g_rbf[m][k][ii] -> s_rbfT[ii][k]
        float4 v = *(const float4*)&g_rbf[(size_t)m * 1024 + tid * 4];
        int k = tid >> 3, ii0 = (tid & 7) * 4;
        s_rbfT[(ii0 + 0) * 36 + k] = v.x; s_rbfT[(ii0 + 1) * 36 + k] = v.y;
        s_rbfT[(ii0 + 2) * 36 + k] = v.z; s_rbfT[(ii0 + 3) * 36 + k] = v.w;
    }
    #pragma unroll
    for (int u = 0; u < 4; u++) {       // 4096 floats = 1024 float4s, 256 threads
        int idx = (tid + u * 256) * 4;
        *(float4*)&s_wk1[idx] = *(const float4*)&Wk1l[idx];
    }
    __syncthreads();

    // hMLP 4x4 tile per thread + gelu + logits partials, all in registers
    int lane = tid & 31, wid = tid >> 5;
    int j0 = lane * 4, k0 = wid * 4;
    float acc[4][4];
    #pragma unroll
    for (int i = 0; i < 4; i++)
        #pragma unroll
        for (int j = 0; j < 4; j++) acc[i][j] = 0.0f;
    #pragma unroll
    for (int ii = 0; ii < 32; ii++) {
        float4 rb = *(const float4*)&s_rbfT[ii * 36 + k0];
        float4 w4 = *(const float4*)&s_wk1[ii * 128 + j0];
        float rr[4] = {rb.x, rb.y, rb.z, rb.w};
        float ww[4] = {w4.x, w4.y, w4.z, w4.w};
        #pragma unroll
        for (int ki = 0; ki < 4; ki++)
            #pragma unroll
            for (int ji = 0; ji < 4; ji++) acc[ki][ji] += rr[ki] * ww[ji];
    }
    float qv4[8][4];
    #pragma unroll
    for (int h = 0; h < 8; h++)
        *(float4*)&qv4[h][0] = *(const float4*)&s_qk[h * 132 + j0];

    const float* ssB = g_ss + (size_t)b * Nn * 256;
    float4 base = *(const float4*)&s_base[j0];
    float v[32];
    #pragma unroll
    for (int ki = 0; ki < 4; ki++) {
        int k = k0 + ki;
        float4 sv = *(const float4*)&ssB[(size_t)s_id[k] * 256 + j0];
        float gl[4];
        gl[0] = gelu_fast(acc[ki][0] + sv.x + base.x);
        gl[1] = gelu_fast(acc[ki][1] + sv.y + base.y);
        gl[2] = gelu_fast(acc[ki][2] + sv.z + base.z);
        gl[3] = gelu_fast(acc[ki][3] + sv.w + base.w);
        #pragma unroll
        for (int h = 0; h < 8; h++) {
            float s = gl[0]*qv4[h][0] + gl[1]*qv4[h][1] + gl[2]*qv4[h][2] + gl[3]*qv4[h][3];
            v[ki * 8 + h] = s;
        }
    }
    // butterfly reduce: lane ends with sum over lanes of v[lane]
    #pragma unroll
    for (int s = 16; s >= 1; s >>= 1) {
        #pragma unroll
        for (int i = 0; i < s; i++) {
            float send = (lane & s) ? v[i] : v[i + s];
            float recv = __shfl_xor_sync(0xffffffffu, send, s);
            v[i] = ((lane & s) ? v[i + s] : v[i]) + recv;
        }
    }
    s_al[(k0 + (lane >> 3)) * 8 + (lane & 7)] = v[0] * 0.17677669529663687f;
    __syncthreads();

    // cutoff-weighted softmax over k, per head
    if (tid < Hh) {
        int h = tid;
        float mx = -3.4e38f;
        for (int k = 0; k < 32; k++) mx = fmaxf(mx, s_al[k * 8 + h]);
        float sum = 0.0f;
        for (int k = 0; k < 32; k++) {
            float w = s_cut[k] * exp_fast(s_al[k * 8 + h] - mx);
            s_al[k * 8 + h] = w;
            sum += w;
        }
        float invs = 1.0f / (sum + 1e-9f);
        for (int k = 0; k < 32; k++) s_al[k * 8 + h] *= invs;
    }
    __syncthreads();

    // agg[d] = sum_k alpha[k,h(d)] * ( vn[src[k],d] + sh[k,:]@WvSh[:,d] )
    {
        int d = tid;
        int h = d >> 5;
        float wv[SHDc];
        #pragma unroll
        for (int s = 0; s < SHDc; s++) wv[s] = WvSh[s * Dd + d];
        const float* vnB = g_qv + (size_t)b * Nn * 512 + 256;
        float acc2 = 0.0f;
        #pragma unroll 4
        for (int k = 0; k < 32; k++) {
            float val = vnB[(size_t)s_id[k] * 512 + d];
            const float* shk = &s_shl[k * SHDc];
            #pragma unroll
            for (int s = 0; s < SHDc; s++) val += shk[s] * wv[s];
            acc2 += s_al[k * 8 + h] * val;
        }
        g_agg[(size_t)m * Dd + d] = acc2;
    }
}

// ---------------- final projection: out = agg @ Wo_out (256x3) ----------------
__global__ void final_kernel(const float* __restrict__ Wo_out, float* __restrict__ out) {
    int gid = blockIdx.x * blockDim.x + threadIdx.x;
    if (gid >= Mm * 3) return;
    int m = gid / 3, c = gid % 3;
    const float* a = g_agg + (size_t)m * Dd;
    float acc = 0.0f;
    #pragma unroll 8
    for (int j = 0; j < Dd; j++) acc += a[j] * Wo_out[j * 3 + c];
    out[gid] = acc;
}

// ---------------- host orchestration ----------------
extern "C" void kernel_launch(void* const* d_in, const int* in_sizes, int n_in,
                              void* d_out, int out_size) {
    const float* x       = (const float*)d_in[0];
    const float* y       = (const float*)d_in[1];
    const float* t       = (const float*)d_in[2];
    const float* W_embed = (const float*)d_in[3];
    const float* Wk1     = (const float*)d_in[4];
    const float* bk1     = (const float*)d_in[5];
    const float* Wk2     = (const float*)d_in[6];
    const float* Wq      = (const float*)d_in[7];
    const float* Wv      = (const float*)d_in[8];
    const float* Wo      = (const float*)d_in[9];
    const float* Wo_out  = (const float*)d_in[10];
    float* out = (float*)d_out;

    float *p_node, *p_qv, *p_ss, *p_agg, *p_wcat1, *p_wcat2;
    cudaGetSymbolAddress((void**)&p_node,  g_node);
    cudaGetSymbolAddress((void**)&p_qv,    g_qv);
    cudaGetSymbolAddress((void**)&p_ss,    g_ss);
    cudaGetSymbolAddress((void**)&p_agg,   g_agg);
    cudaGetSymbolAddress((void**)&p_wcat1, g_wcat1);
    cudaGetSymbolAddress((void**)&p_wcat2, g_wcat2);

    knn_kernel<<<dim3(Nn / 8, Bb), 256>>>(x);
    geom_kernel<<<(Mm * Kk + 255) / 256, 256>>>(x);
    embed_kernel<<<Mm, Dd>>>(y, t, W_embed);
    tpart_kernel<<<Lc * Bb, HIDc>>>(t, Wk1, bk1);
    pack_kernel<<<(Lc * 256 * 512 + Lc * 128 * 256) / 256, 256>>>(Wq, Wv, Wk1);

    for (int l = 0; l < Lc; l++) {
        // [q | vn] = node @ wcat1[l]   (8192 x 512 x 256)
        gemm_big<<<dim3(Mm / 128, 512 / 128), 256>>>(
            p_node, Dd, p_wcat1 + (size_t)l * 256 * 512, 512,
            p_qv, 512, 256, nullptr, 0);
        // [ssrc | sdst] = node[:, :128] @ wcat2[l]   (8192 x 256 x 128)
        gemm_big<<<dim3(Mm / 128, 256 / 128), 256>>>(
            p_node, Dd, p_wcat2 + (size_t)l * 128 * 256, 256,
            p_ss, 256, 128, nullptr, 0);
        // qk[m][h][j] batched over heads
        qk_kernel<<<dim3(Mm / 64, Hh), 256>>>(Wk2, l);
        // fused edge MLP + attention + aggregation
        edge_kernel<<<Mm, 256>>>(Wk1, Wv, l);

        if (l < Lc - 1) {
            // node = act(node + agg @ Wo[l])
            gemm_big<<<dim3(Mm / 128, 256 / 128), 256>>>(
                p_agg, Dd, Wo + (size_t)l * Dd * Dd, Dd,
                p_node, Dd, 256, p_node, 1);
        } else {
            final_kernel<<<(Mm * 3 + 255) / 256, 256>>>(Wo_out, out);
        }
    }
}

// round 6
// speedup vs baseline: 3.9865x; 1.3754x over previous
#include <cuda_runtime.h>
#include <math.h>
#include <stdint.h>

// ---------------- problem dims ----------------
#define Bb    8
#define Nn    1024
#define Kk    32
#define Dd    256
#define Hh    8
#define DHh   32
#define TDIMc 16
#define NBc   32
#define HIDc  128
#define Lc    4
#define NSc   128
#define SHDc  9
#define EINc  304
#define Mm    (Bb*Nn)

// ---------------- scratch (device globals; no allocs allowed) ----------------
__device__ int   g_src [Mm*Kk];
__device__ float g_cutb[Mm*Kk];
__device__ float g_sh  [Mm*Kk*SHDc];
__device__ float g_rbf [Mm*Kk*NBc];     // rbf*cut, layer-invariant
__device__ float g_node[Mm*Dd];
__device__ float g_qv  [Mm*512];        // [m][0:256]=q, [m][256:512]=vn
__device__ float g_ss  [Mm*256];        // [m][0:128]=ssrc, [m][128:256]=sdst
__device__ float g_agg [Mm*Dd];
__device__ float g_qk  [Mm*Hh*HIDc];    // [m][h][j]
__device__ float g_tpart[Lc*Bb*HIDc];
__device__ float g_wcat1[Lc*256*512];   // [l][k][ Wq | Wv_top ]
__device__ float g_wcat2[Lc*128*256];   // [l][k][ Wk1_src | Wk1_dst ]

// ---------------- FFMA-only fast math (no MUFU in hot paths) ----------------
__device__ __forceinline__ float fast_rcp(float q) {
    float r = __int_as_float(0x7EF311C3 - __float_as_int(q));
    r = r * (2.0f - q * r);
    r = r * (2.0f - q * r);
    r = r * (2.0f - q * r);
    return r;
}
__device__ __forceinline__ float tanh_fast(float x) {
    x = fminf(fmaxf(x, -7.90531110591f), 7.90531110591f);
    float x2 = x * x;
    float p = fmaf(x2, -2.76076847742355e-16f, 2.00018790482477e-13f);
    p = fmaf(x2, p, -8.60467152213735e-11f);
    p = fmaf(x2, p,  5.12229709037114e-08f);
    p = fmaf(x2, p,  1.48572235717979e-05f);
    p = fmaf(x2, p,  6.37261928875436e-04f);
    p = fmaf(x2, p,  4.89352455891786e-03f);
    p = p * x;
    float q = fmaf(x2, 1.19825839466702e-06f, 1.18534705686654e-04f);
    q = fmaf(x2, q, 2.26843463243900e-03f);
    q = fmaf(x2, q, 4.89352518554385e-03f);
    return p * fast_rcp(q);
}
__device__ __forceinline__ float gelu_fast(float v) {
    float c = v * fmaf(v * v, 0.0356774081363f, 0.7978845608028654f);
    return 0.5f * v * (1.0f + tanh_fast(c));
}
__device__ __forceinline__ float exp_fast(float x) {   // expects x <= 0
    x = fmaxf(x, -80.0f);
    float y = x * 1.4426950408889634f;
    float n = floorf(y);
    float f = y - n;
    float p = 1.5252733804059838e-5f;
    p = fmaf(p, f, 1.5403530393381606e-4f);
    p = fmaf(p, f, 1.3333558146428443e-3f);
    p = fmaf(p, f, 9.618129107628477e-3f);
    p = fmaf(p, f, 5.550410866482158e-2f);
    p = fmaf(p, f, 2.402265069591007e-1f);
    p = fmaf(p, f, 6.931471805599453e-1f);
    p = fmaf(p, f, 1.0f);
    return p * __int_as_float(((int)n + 127) << 23);
}
__device__ __forceinline__ uint32_t f2tf32(float f) {
    uint32_t u;
    asm("cvt.rna.tf32.f32 %0, %1;" : "=r"(u) : "f"(f));
    return u;
}
__device__ __forceinline__ void mma_tf32(float c[4], uint32_t a0, uint32_t a1,
                                         uint32_t a2, uint32_t a3,
                                         uint32_t b0, uint32_t b1) {
    asm volatile(
        "mma.sync.aligned.m16n8k8.row.col.f32.tf32.tf32.f32 "
        "{%0,%1,%2,%3}, {%4,%5,%6,%7}, {%8,%9}, {%0,%1,%2,%3};"
        : "+f"(c[0]), "+f"(c[1]), "+f"(c[2]), "+f"(c[3])
        : "r"(a0), "r"(a1), "r"(a2), "r"(a3), "r"(b0), "r"(b1));
}

// ---------------- warp-collective kNN: lane-held top-32, unsorted ----------------
__global__ void knn_kernel(const float* __restrict__ x) {
    __shared__ float px[Nn], py[Nn], pz[Nn];
    int b = blockIdx.y;
    const float* xb = x + (size_t)b * Nn * 3;
    for (int i = threadIdx.x; i < Nn; i += blockDim.x) {
        px[i] = xb[i*3+0]; py[i] = xb[i*3+1]; pz[i] = xb[i*3+2];
    }
    __syncthreads();
    int warp = threadIdx.x >> 5, lane = threadIdx.x & 31;
    int n = blockIdx.x * 8 + warp;
    float qx = px[n], qy = py[n], qz = pz[n];

    float dx = qx - px[lane], dy = qy - py[lane], dz = qz - pz[lane];
    float best_d = dx*dx + dy*dy + dz*dz;
    int   best_i = lane;
    float thr = best_d;
    #pragma unroll
    for (int off = 16; off; off >>= 1) thr = fmaxf(thr, __shfl_xor_sync(~0u, thr, off));

    for (int j0 = 32; j0 < Nn; j0 += 32) {
        int j = j0 + lane;
        dx = qx - px[j]; dy = qy - py[j]; dz = qz - pz[j];
        float d2 = dx*dx + dy*dy + dz*dz;
        unsigned mask = __ballot_sync(~0u, d2 < thr);
        while (mask) {
            int src = __ffs(mask) - 1; mask &= mask - 1;
            float cd = __shfl_sync(~0u, d2, src);
            int   ci = j0 + src;
            float m = best_d; int ml = lane;
            #pragma unroll
            for (int off = 16; off; off >>= 1) {
                float om = __shfl_xor_sync(~0u, m, off);
                int  oml = __shfl_xor_sync(~0u, ml, off);
                if (om > m || (om == m && oml > ml)) { m = om; ml = oml; }
            }
            if (cd < m) {
                if (lane == ml) { best_d = cd; best_i = ci; }
            }
            thr = m;
        }
    }
    g_src[(b * Nn + n) * Kk + lane] = best_i;
}

// ---------------- per-edge geometry: cutoff, sh, rbf*cut (precomputed) ----------------
__global__ void geom_kernel(const float* __restrict__ x) {
    int gid = blockIdx.x * blockDim.x + threadIdx.x;
    if (gid >= Mm * Kk) return;
    int m = gid / Kk;
    int b = m / Nn, n = m % Nn;
    int s = g_src[gid];
    const float* xb = x + (size_t)b * Nn * 3;
    float vx = xb[n*3+0] - xb[s*3+0];
    float vy = xb[n*3+1] - xb[s*3+1];
    float vz = xb[n*3+2] - xb[s*3+2];
    float r = sqrtf(vx*vx + vy*vy + vz*vz);
    float xc = 10.0f - 5.0f * r;
    float cut = (xc > 0.0f) ? 1.4f * exp_fast(-fast_rcp(xc)) : 0.0f;
    g_cutb[gid] = cut;
    float inv = 1.0f / fmaxf(r, 1e-9f);
    float ux = vx * inv, uy = vy * inv, uz = vz * inv;
    const float s3 = 1.7320508075688772f;
    const float s15 = 3.872983346207417f;
    const float h5 = 1.118033988749895f;
    const float h15 = 1.9364916731037085f;
    float* sh = g_sh + (size_t)gid * SHDc;
    sh[0] = 1.0f;
    sh[1] = s3 * ux; sh[2] = s3 * uy; sh[3] = s3 * uz;
    sh[4] = s15 * ux * uy;
    sh[5] = s15 * uy * uz;
    sh[6] = h5 * (3.0f * uz * uz - 1.0f);
    sh[7] = s15 * ux * uz;
    sh[8] = h15 * (ux * ux - uy * uy);
    const float ISTEP = 15.5f;
    const float RBFC  = 5.656854249492381f * 0.95f / 1.12f;
    float base = r * ISTEP;
    float rb[NBc];
    #pragma unroll
    for (int ii = 0; ii < NBc; ii++) {
        float d = base - (float)ii;
        rb[ii] = exp_fast(-d * d) * RBFC * cut;
    }
    float4* dst = (float4*)(g_rbf + (size_t)gid * NBc);
    #pragma unroll
    for (int u = 0; u < 8; u++)
        dst[u] = make_float4(rb[u*4], rb[u*4+1], rb[u*4+2], rb[u*4+3]);
}

// ---------------- node embedding: [y,t] @ W_embed (19x256) ----------------
__global__ void embed_kernel(const float* __restrict__ y, const float* __restrict__ t,
                             const float* __restrict__ W_embed) {
    __shared__ float in[3 + TDIMc];
    int m = blockIdx.x;
    int b = m / Nn;
    int tid = threadIdx.x;
    if (tid < 3) in[tid] = y[(size_t)m * 3 + tid];
    else if (tid < 3 + TDIMc) in[tid] = t[b * TDIMc + (tid - 3)];
    __syncthreads();
    float acc = 0.0f;
    #pragma unroll
    for (int i = 0; i < 3 + TDIMc; i++) acc += in[i] * W_embed[i * Dd + tid];
    g_node[(size_t)m * Dd + tid] = acc;
}

// ---------------- tpart[l][b][j] = bk1[l][j] + t[b]@Wk1[l][32:48][j] ----------------
__global__ void tpart_kernel(const float* __restrict__ t, const float* __restrict__ Wk1,
                             const float* __restrict__ bk1) {
    int l = blockIdx.x / Bb, b = blockIdx.x % Bb;
    int j = threadIdx.x;
    float acc = bk1[l * HIDc + j];
    #pragma unroll
    for (int i = 0; i < TDIMc; i++)
        acc += t[b * TDIMc + i] * Wk1[((size_t)l * EINc + 32 + i) * HIDc + j];
    g_tpart[(l * Bb + b) * HIDc + j] = acc;
}

// ---------------- pack weights ----------------
__global__ void pack_kernel(const float* __restrict__ Wq, const float* __restrict__ Wv,
                            const float* __restrict__ Wk1) {
    int i = blockIdx.x * 256 + threadIdx.x;
    const int SZ1 = Lc * 256 * 512;
    if (i < SZ1) {
        int l = i / (256 * 512);
        int r = (i >> 9) & 255;
        int n = i & 511;
        float v = (n < 256) ? Wq[((size_t)l * 256 + r) * 256 + n]
                            : Wv[((size_t)l * (Dd + SHDc) + r) * 256 + (n - 256)];
        g_wcat1[i] = v;
    } else {
        int j = i - SZ1;
        int l = j / (128 * 256);
        int r = (j >> 8) & 127;
        int n = j & 255;
        int row = (n < 128) ? (48 + r) : (176 + r);
        g_wcat2[j] = Wk1[((size_t)l * EINc + row) * HIDc + (n & 127)];
    }
}

// ---------------- TF32 tensor-core GEMM: 128x128 tile, 8 warps (64x32 each) -------
// C[m*ldc+n] = A[m*lda+:] @ W[:*ldw+n]; actmode 1: resid + gelu/tanh/id epilogue.
__global__ void gemm_tc(const float* __restrict__ A, int lda,
                        const float* __restrict__ W, int ldw,
                        float* __restrict__ C, int ldc, int Kd,
                        const float* __restrict__ resid, int actmode) {
    __shared__ uint32_t sA[32 * 132];   // [k][m], tf32
    __shared__ uint32_t sB[32 * 132];   // [k][n], tf32
    int m0 = blockIdx.x * 128, n0 = blockIdx.y * 128;
    int tid = threadIdx.x, lane = tid & 31, wid = tid >> 5;
    int wm = (wid & 1) * 64, wn = (wid >> 1) * 32;
    int gp = lane >> 2, tg = lane & 3;

    float c[4][4][4];
    #pragma unroll
    for (int i = 0; i < 4; i++)
        #pragma unroll
        for (int j = 0; j < 4; j++)
            #pragma unroll
            for (int r = 0; r < 4; r++) c[i][j][r] = 0.0f;

    for (int kt = 0; kt < Kd; kt += 32) {
        #pragma unroll
        for (int u = 0; u < 4; u++) {           // A: 128 m x 8 f4(k)
            int id = tid + u * 256;
            int mm = id >> 3, kq = (id & 7) * 4;
            float4 v = *(const float4*)&A[(size_t)(m0 + mm) * lda + kt + kq];
            sA[(kq + 0) * 132 + mm] = f2tf32(v.x);
            sA[(kq + 1) * 132 + mm] = f2tf32(v.y);
            sA[(kq + 2) * 132 + mm] = f2tf32(v.z);
            sA[(kq + 3) * 132 + mm] = f2tf32(v.w);
        }
        #pragma unroll
        for (int u = 0; u < 4; u++) {           // B: 32 k x 32 f4(n)
            int id = tid + u * 256;
            int kk = id >> 5, nq = (id & 31) * 4;
            float4 v = *(const float4*)&W[(size_t)(kt + kk) * ldw + n0 + nq];
            uint4 o;
            o.x = f2tf32(v.x); o.y = f2tf32(v.y); o.z = f2tf32(v.z); o.w = f2tf32(v.w);
            *(uint4*)&sB[kk * 132 + nq] = o;
        }
        __syncthreads();
        #pragma unroll
        for (int ka = 0; ka < 4; ka++) {
            int kb = ka * 8;
            uint32_t bf[4][2];
            #pragma unroll
            for (int na = 0; na < 4; na++) {
                bf[na][0] = sB[(kb + tg) * 132 + wn + na * 8 + gp];
                bf[na][1] = sB[(kb + tg + 4) * 132 + wn + na * 8 + gp];
            }
            #pragma unroll
            for (int ma = 0; ma < 4; ma++) {
                int mb = wm + ma * 16 + gp;
                uint32_t a0 = sA[(kb + tg) * 132 + mb];
                uint32_t a1 = sA[(kb + tg) * 132 + mb + 8];
                uint32_t a2 = sA[(kb + tg + 4) * 132 + mb];
                uint32_t a3 = sA[(kb + tg + 4) * 132 + mb + 8];
                #pragma unroll
                for (int na = 0; na < 4; na++)
                    mma_tf32(c[ma][na], a0, a1, a2, a3, bf[na][0], bf[na][1]);
            }
        }
        __syncthreads();
    }

    // epilogue: c0,c1 at (row, col..col+1); c2,c3 at (row+8, ...)
    #pragma unroll
    for (int ma = 0; ma < 4; ma++) {
        int row = m0 + wm + ma * 16 + gp;
        #pragma unroll
        for (int na = 0; na < 4; na++) {
            int col = n0 + wn + na * 8 + 2 * tg;
            #pragma unroll
            for (int half = 0; half < 2; half++) {
                int rr = row + half * 8;
                float v0 = c[ma][na][half * 2 + 0];
                float v1 = c[ma][na][half * 2 + 1];
                if (actmode == 1) {
                    float2 rs = *(const float2*)&resid[(size_t)rr * ldc + col];
                    v0 += rs.x; v1 += rs.y;
                    if (col < 64)       { v0 = gelu_fast(v0); v1 = gelu_fast(v1); }
                    else if (col < 128) { v0 = tanh_fast(v0); v1 = tanh_fast(v1); }
                }
                float2 o = make_float2(v0, v1);
                *(float2*)&C[(size_t)rr * ldc + col] = o;
            }
        }
    }
}

// ---------------- batched per-head qk GEMM: qk[m][h][j] = q[m,h,:]·Wk2[j,h,:] -------
__global__ void qk_kernel(const float* __restrict__ Wk2, int l) {
    __shared__ float qsT[32 * 68];    // [d][m]
    __shared__ float wsT[32 * 132];   // [d][j]
    int m0 = blockIdx.x * 64;
    int h = blockIdx.y;
    int tid = threadIdx.x;
    const float* W = Wk2 + (size_t)l * HIDc * Dd;
    #pragma unroll
    for (int u = 0; u < 2; u++) {
        int id = tid * 2 + u;
        int row = id >> 3, c4 = (id & 7) * 4;
        float4 v = *(const float4*)&g_qv[(size_t)(m0 + row) * 512 + h * 32 + c4];
        qsT[(c4 + 0) * 68 + row] = v.x; qsT[(c4 + 1) * 68 + row] = v.y;
        qsT[(c4 + 2) * 68 + row] = v.z; qsT[(c4 + 3) * 68 + row] = v.w;
    }
    #pragma unroll
    for (int u = 0; u < 4; u++) {
        int id = tid * 4 + u;
        int j = id >> 3, c4 = (id & 7) * 4;
        float4 v = *(const float4*)&W[(size_t)j * 256 + h * 32 + c4];
        wsT[(c4 + 0) * 132 + j] = v.x; wsT[(c4 + 1) * 132 + j] = v.y;
        wsT[(c4 + 2) * 132 + j] = v.z; wsT[(c4 + 3) * 132 + j] = v.w;
    }
    __syncthreads();
    int tx = tid & 31, ty = tid >> 5;
    float acc[8][4];
    #pragma unroll
    for (int i = 0; i < 8; i++)
        #pragma unroll
        for (int j = 0; j < 4; j++) acc[i][j] = 0.0f;
    #pragma unroll
    for (int d = 0; d < 32; d++) {
        float4 a0 = *(const float4*)&qsT[d * 68 + ty * 8];
        float4 a1 = *(const float4*)&qsT[d * 68 + ty * 8 + 4];
        float4 bv = *(const float4*)&wsT[d * 132 + tx * 4];
        float am[8] = {a0.x, a0.y, a0.z, a0.w, a1.x, a1.y, a1.z, a1.w};
        float bm[4] = {bv.x, bv.y, bv.z, bv.w};
        #pragma unroll
        for (int i = 0; i < 8; i++)
            #pragma unroll
            for (int j = 0; j < 4; j++) acc[i][j] += am[i] * bm[j];
    }
    #pragma unroll
    for (int i = 0; i < 8; i++) {
        float4 o = make_float4(acc[i][0], acc[i][1], acc[i][2], acc[i][3]);
        *(float4*)&g_qk[(size_t)(m0 + ty * 8 + i) * 1024 + h * 128 + tx * 4] = o;
    }
}

// ---------------- fused edge kernel ----------------
__global__ void edge_kernel(const float* __restrict__ Wk1, const float* __restrict__ Wv,
                            int l) {
    __shared__ float s_wk1[32 * 128];   // [ii][j]
    __shared__ float s_rbfT[32 * 36];   // [ii][k]
    __shared__ float s_qk [8 * 132];    // [h][j]
    __shared__ float s_al [32 * 8];     // [k][h]
    __shared__ float s_shl[32 * 9];     // [k][s]
    __shared__ float s_wvsh[9 * 256];   // [s][d]
    __shared__ float s_asum[Hh * SHDc]; // [h][s]
    __shared__ float s_base[128];
    __shared__ float s_cut[32];
    __shared__ int   s_id[32];

    int m = blockIdx.x;
    int b = m >> 10;
    int tid = threadIdx.x;
    const float* Wk1l = Wk1 + (size_t)l * EINc * HIDc;
    const float* WvSh = Wv + ((size_t)l * (Dd + SHDc) + Dd) * Dd;
    const float* tpl  = g_tpart + (l * Bb + b) * HIDc;

    if (tid < 32) {
        s_id[tid]  = g_src [m * 32 + tid];
        s_cut[tid] = g_cutb[m * 32 + tid];
    }
    if (tid < 128) s_base[tid] = g_ss[(size_t)m * 256 + 128 + tid] + tpl[tid];
    for (int i = tid; i < 1024; i += 256) {
        int h = i >> 7, j = i & 127;
        s_qk[h * 132 + j] = g_qk[(size_t)m * 1024 + i];
    }
    for (int i = tid; i < 32 * SHDc; i += 256) s_shl[i] = g_sh[(size_t)m * 32 * SHDc + i];
    {   // rbf load + transpose
        float4 v = *(const float4*)&g_rbf[(size_t)m * 1024 + tid * 4];
        int k = tid >> 3, ii0 = (tid & 7) * 4;
        s_rbfT[(ii0 + 0) * 36 + k] = v.x; s_rbfT[(ii0 + 1) * 36 + k] = v.y;
        s_rbfT[(ii0 + 2) * 36 + k] = v.z; s_rbfT[(ii0 + 3) * 36 + k] = v.w;
    }
    #pragma unroll
    for (int u = 0; u < 4; u++) {       // 4096 floats = 1024 float4s
        int idx = (tid + u * 256) * 4;
        *(float4*)&s_wk1[idx] = *(const float4*)&Wk1l[idx];
    }
    #pragma unroll
    for (int u = 0; u < 3; u++) {       // WvSh: 2304 floats = 576 f4
        int i = tid + u * 256;
        if (i < 576) *(float4*)&s_wvsh[i * 4] = *(const float4*)&WvSh[i * 4];
    }
    __syncthreads();

    // hMLP 4x4 tile per thread + gelu + logits partials
    int lane = tid & 31, wid = tid >> 5;
    int j0 = lane * 4, k0 = wid * 4;
    float acc[4][4];
    #pragma unroll
    for (int i = 0; i < 4; i++)
        #pragma unroll
        for (int j = 0; j < 4; j++) acc[i][j] = 0.0f;
    #pragma unroll
    for (int ii = 0; ii < 32; ii++) {
        float4 rb = *(const float4*)&s_rbfT[ii * 36 + k0];
        float4 w4 = *(const float4*)&s_wk1[ii * 128 + j0];
        float rr[4] = {rb.x, rb.y, rb.z, rb.w};
        float ww[4] = {w4.x, w4.y, w4.z, w4.w};
        #pragma unroll
        for (int ki = 0; ki < 4; ki++)
            #pragma unroll
            for (int ji = 0; ji < 4; ji++) acc[ki][ji] += rr[ki] * ww[ji];
    }
    float qv4[8][4];
    #pragma unroll
    for (int h = 0; h < 8; h++)
        *(float4*)&qv4[h][0] = *(const float4*)&s_qk[h * 132 + j0];

    const float* ssB = g_ss + (size_t)b * Nn * 256;
    float4 base = *(const float4*)&s_base[j0];
    float v[32];
    #pragma unroll
    for (int ki = 0; ki < 4; ki++) {
        int k = k0 + ki;
        float4 sv = *(const float4*)&ssB[(size_t)s_id[k] * 256 + j0];
        float gl[4];
        gl[0] = gelu_fast(acc[ki][0] + sv.x + base.x);
        gl[1] = gelu_fast(acc[ki][1] + sv.y + base.y);
        gl[2] = gelu_fast(acc[ki][2] + sv.z + base.z);
        gl[3] = gelu_fast(acc[ki][3] + sv.w + base.w);
        #pragma unroll
        for (int h = 0; h < 8; h++) {
            float s = gl[0]*qv4[h][0] + gl[1]*qv4[h][1] + gl[2]*qv4[h][2] + gl[3]*qv4[h][3];
            v[ki * 8 + h] = s;
        }
    }
    #pragma unroll
    for (int s = 16; s >= 1; s >>= 1) {
        #pragma unroll
        for (int i = 0; i < s; i++) {
            float send = (lane & s) ? v[i] : v[i + s];
            float recv = __shfl_xor_sync(0xffffffffu, send, s);
            v[i] = ((lane & s) ? v[i + s] : v[i]) + recv;
        }
    }
    s_al[(k0 + (lane >> 3)) * 8 + (lane & 7)] = v[0] * 0.17677669529663687f;
    __syncthreads();

    // cutoff-weighted softmax over k, per head
    if (tid < Hh) {
        int h = tid;
        float mx = -3.4e38f;
        for (int k = 0; k < 32; k++) mx = fmaxf(mx, s_al[k * 8 + h]);
        float sum = 0.0f;
        for (int k = 0; k < 32; k++) {
            float w = s_cut[k] * exp_fast(s_al[k * 8 + h] - mx);
            s_al[k * 8 + h] = w;
            sum += w;
        }
        float invs = 1.0f / (sum + 1e-9f);
        for (int k = 0; k < 32; k++) s_al[k * 8 + h] *= invs;
    }
    __syncthreads();

    // asum[h][s] = sum_k alpha[k,h] * sh[k,s]
    if (tid < Hh * SHDc) {
        int h = tid / SHDc, s = tid % SHDc;
        float a = 0.0f;
        #pragma unroll 8
        for (int k = 0; k < 32; k++) a += s_al[k * 8 + h] * s_shl[k * SHDc + s];
        s_asum[tid] = a;
    }
    __syncthreads();

    // agg[d] = sum_k alpha[k,h(d)]*vn[src[k],d] + sum_s asum[h,s]*WvSh[s,d]
    {
        int d = tid;
        int h = d >> 5;
        const float* vnB = g_qv + (size_t)b * Nn * 512 + 256;
        float acc2 = 0.0f;
        #pragma unroll 8
        for (int k = 0; k < 32; k++)
            acc2 += s_al[k * 8 + h] * vnB[(size_t)s_id[k] * 512 + d];
        float proj = 0.0f;
        #pragma unroll
        for (int s = 0; s < SHDc; s++) proj += s_asum[h * SHDc + s] * s_wvsh[s * 256 + d];
        g_agg[(size_t)m * Dd + d] = acc2 + proj;
    }
}

// ---------------- final projection: out = agg @ Wo_out (256x3) ----------------
__global__ void final_kernel(const float* __restrict__ Wo_out, float* __restrict__ out) {
    int gid = blockIdx.x * blockDim.x + threadIdx.x;
    if (gid >= Mm * 3) return;
    int m = gid / 3, c = gid % 3;
    const float* a = g_agg + (size_t)m * Dd;
    float acc = 0.0f;
    #pragma unroll 8
    for (int j = 0; j < Dd; j++) acc += a[j] * Wo_out[j * 3 + c];
    out[gid] = acc;
}

// ---------------- host orchestration ----------------
extern "C" void kernel_launch(void* const* d_in, const int* in_sizes, int n_in,
                              void* d_out, int out_size) {
    const float* x       = (const float*)d_in[0];
    const float* y       = (const float*)d_in[1];
    const float* t       = (const float*)d_in[2];
    const float* W_embed = (const float*)d_in[3];
    const float* Wk1     = (const float*)d_in[4];
    const float* bk1     = (const float*)d_in[5];
    const float* Wk2     = (const float*)d_in[6];
    const float* Wq      = (const float*)d_in[7];
    const float* Wv      = (const float*)d_in[8];
    const float* Wo      = (const float*)d_in[9];
    const float* Wo_out  = (const float*)d_in[10];
    float* out = (float*)d_out;

    float *p_node, *p_qv, *p_ss, *p_agg, *p_wcat1, *p_wcat2;
    cudaGetSymbolAddress((void**)&p_node,  g_node);
    cudaGetSymbolAddress((void**)&p_qv,    g_qv);
    cudaGetSymbolAddress((void**)&p_ss,    g_ss);
    cudaGetSymbolAddress((void**)&p_agg,   g_agg);
    cudaGetSymbolAddress((void**)&p_wcat1, g_wcat1);
    cudaGetSymbolAddress((void**)&p_wcat2, g_wcat2);

    knn_kernel<<<dim3(Nn / 8, Bb), 256>>>(x);
    geom_kernel<<<(Mm * Kk + 255) / 256, 256>>>(x);
    embed_kernel<<<Mm, Dd>>>(y, t, W_embed);
    tpart_kernel<<<Lc * Bb, HIDc>>>(t, Wk1, bk1);
    pack_kernel<<<(Lc * 256 * 512 + Lc * 128 * 256) / 256, 256>>>(Wq, Wv, Wk1);

    for (int l = 0; l < Lc; l++) {
        // [q | vn] = node @ wcat1[l]   (8192 x 512 x 256)
        gemm_tc<<<dim3(Mm / 128, 512 / 128), 256>>>(
            p_node, Dd, p_wcat1 + (size_t)l * 256 * 512, 512,
            p_qv, 512, 256, nullptr, 0);
        // [ssrc | sdst] = node[:, :128] @ wcat2[l]   (8192 x 256 x 128)
        gemm_tc<<<dim3(Mm / 128, 256 / 128), 256>>>(
            p_node, Dd, p_wcat2 + (size_t)l * 128 * 256, 256,
            p_ss, 256, 128, nullptr, 0);
        // qk[m][h][j] batched over heads
        qk_kernel<<<dim3(Mm / 64, Hh), 256>>>(Wk2, l);
        // fused edge MLP + attention + aggregation
        edge_kernel<<<Mm, 256>>>(Wk1, Wv, l);

        if (l < Lc - 1) {
            // node = act(node + agg @ Wo[l])
            gemm_tc<<<dim3(Mm / 128, 256 / 128), 256>>>(
                p_agg, Dd, Wo + (size_t)l * Dd * Dd, Dd,
                p_node, Dd, 256, p_node, 1);
        } else {
            final_kernel<<<(Mm * 3 + 255) / 256, 256>>>(Wo_out, out);
        }
    }
}